// round 8
// baseline (speedup 1.0000x reference)
#include <cuda_runtime.h>
#include <cuda_bf16.h>
#include <cstdint>

#define Bb 32
#define Ll 1024
#define LMD 1024
#define Dd 128
#define Rr 3
#define NLAYERS 2
#define Cc 8
#define Nn (Bb*Ll)          // 32768
#define Ee 524288
#define NRr (Nn*Rr)         // 98304

// ---------------- scratch (device globals; no allocations allowed) ----------
__device__ float g_lm[Nn*Dd];        // post-LN lm features
__device__ float g_x[Nn*Dd];         // layer buffers
__device__ float g_x2[Nn*Dd];
__device__ float g_agg[(size_t)Nn*Rr*Dd]; // [N][R*D] mean-aggregated
__device__ float g_Wt[LMD*Dd];       // lm_W transposed -> [K=1024][128]
__device__ float g_logits_scratch[Nn*Cc];
__device__ int   g_cnt[NRr];
__device__ int   g_cursor[NRr];
__device__ int   g_off[NRr+1];
__device__ int   g_srcs[Ee];
__device__ float g_loss[2];          // {sum_nll, n_valid}
__device__ int   g_is64;             // 1 if int inputs are int64, 0 if int32

// ---------------- int dtype probe ----------------
// If data is int64 (values < 2^31, nonneg), every odd 32-bit word is 0.
// For random int32 node ids, the chance all 1024 sampled odd words are 0 is ~0.
__global__ void probe_k(const int* __restrict__ p) {
    __shared__ int bad;
    if (threadIdx.x == 0) bad = 0;
    __syncthreads();
    for (int i = threadIdx.x; i < 1024; i += blockDim.x)
        if (p[2*i + 1] != 0) bad = 1;
    __syncthreads();
    if (threadIdx.x == 0) g_is64 = bad ? 0 : 1;
}

__device__ __forceinline__ int load_int(const void* p, long long idx) {
    if (g_is64) return (int)((const long long*)p)[idx];
    return ((const int*)p)[idx];
}

// ---------------- utility kernels ----------------
__global__ void zero_k() {
    int i = blockIdx.x*blockDim.x + threadIdx.x;
    int stride = gridDim.x*blockDim.x;
    for (; i < NRr; i += stride) { g_cnt[i] = 0; g_cursor[i] = 0; }
    if (blockIdx.x == 0 && threadIdx.x < 2) g_loss[threadIdx.x] = 0.f;
}

__global__ void transW_k(const float* __restrict__ W) {   // W [128][1024] -> Wt [1024][128]
    int i = blockIdx.x*blockDim.x + threadIdx.x;          // 131072 elems
    if (i >= LMD*Dd) return;
    int h = i >> 10, k = i & 1023;
    g_Wt[k*Dd + h] = W[i];
}

// ---------------- GEMM: C[M x 128] = relu(A1@B1 + A2@B2 + bias) --------------
// A row-major [M x K], B row-major [K x 128]. BM=BN=128, BK=16, 256 thr, 8x8 microtile.
__global__ __launch_bounds__(256, 2)
void gemm_k(const float* __restrict__ A1, int K1, const float* __restrict__ B1,
            const float* __restrict__ A2, int K2, const float* __restrict__ B2,
            const float* __restrict__ bias, float* __restrict__ C)
{
    __shared__ float As[16][132];   // [k][m], stride 132 keeps 16B alignment
    __shared__ float Bs[16][128];   // [k][n]

    const int tid = threadIdx.x;
    const int ty  = tid >> 4;       // 0..15 row group
    const int txx = tid & 15;       // 0..15 col group
    const int m0  = blockIdx.x * 128;

    const int lrow = tid >> 1;      // 0..127   (A tile load)
    const int lk   = (tid & 1) * 8; // 0 or 8

    float acc[8][8];
#pragma unroll
    for (int i = 0; i < 8; i++)
#pragma unroll
        for (int j = 0; j < 8; j++) acc[i][j] = 0.f;

#pragma unroll 1
    for (int part = 0; part < 2; part++) {
        const float* A  = part ? A2 : A1;
        const float* Bm = part ? B2 : B1;
        const int K     = part ? K2 : K1;
        if (K == 0 || A == nullptr) continue;

#pragma unroll 1
        for (int kt = 0; kt < K; kt += 16) {
            // load A tile: row m0+lrow, cols kt+lk..+7
            const float* ap = A + (size_t)(m0 + lrow) * K + kt + lk;
            float4 a0 = *(const float4*)(ap);
            float4 a1 = *(const float4*)(ap + 4);
            As[lk+0][lrow] = a0.x; As[lk+1][lrow] = a0.y;
            As[lk+2][lrow] = a0.z; As[lk+3][lrow] = a0.w;
            As[lk+4][lrow] = a1.x; As[lk+5][lrow] = a1.y;
            As[lk+6][lrow] = a1.z; As[lk+7][lrow] = a1.w;
            // load B tile: contiguous 16x128 block
            const float4* bp = (const float4*)(Bm + (size_t)kt * 128);
            float4* bs4 = (float4*)&Bs[0][0];
            bs4[tid]       = bp[tid];
            bs4[tid + 256] = bp[tid + 256];
            __syncthreads();

#pragma unroll
            for (int kk = 0; kk < 16; kk++) {
                float4 fa0 = *(const float4*)&As[kk][ty*8];
                float4 fa1 = *(const float4*)&As[kk][ty*8 + 4];
                float4 fb0 = *(const float4*)&Bs[kk][txx*8];
                float4 fb1 = *(const float4*)&Bs[kk][txx*8 + 4];
                float a[8] = {fa0.x,fa0.y,fa0.z,fa0.w, fa1.x,fa1.y,fa1.z,fa1.w};
                float b[8] = {fb0.x,fb0.y,fb0.z,fb0.w, fb1.x,fb1.y,fb1.z,fb1.w};
#pragma unroll
                for (int i = 0; i < 8; i++)
#pragma unroll
                    for (int j = 0; j < 8; j++)
                        acc[i][j] = fmaf(a[i], b[j], acc[i][j]);
            }
            __syncthreads();
        }
    }

    // epilogue: +bias, relu, store
    float bcol[8];
#pragma unroll
    for (int j = 0; j < 8; j++) bcol[j] = bias[txx*8 + j];
#pragma unroll
    for (int i = 0; i < 8; i++) {
        int row = m0 + ty*8 + i;
        float* cp = C + (size_t)row * 128 + txx*8;
        float v[8];
#pragma unroll
        for (int j = 0; j < 8; j++) v[j] = fmaxf(acc[i][j] + bcol[j], 0.f);
        *(float4*)(cp)     = make_float4(v[0], v[1], v[2], v[3]);
        *(float4*)(cp + 4) = make_float4(v[4], v[5], v[6], v[7]);
    }
}

// ---------------- LayerNorm over D=128, one warp per row ----------------
__global__ void ln_k(const float* __restrict__ in, const float* __restrict__ gam,
                     const float* __restrict__ bet, float* __restrict__ out)
{
    int wid = threadIdx.x >> 5, lane = threadIdx.x & 31;
    int row = blockIdx.x * 8 + wid;
    const float4* ip = (const float4*)(in + (size_t)row * 128);
    float4 v = ip[lane];
    float s  = v.x + v.y + v.z + v.w;
    float sq = v.x*v.x + v.y*v.y + v.z*v.z + v.w*v.w;
#pragma unroll
    for (int o = 16; o; o >>= 1) {
        s  += __shfl_xor_sync(0xffffffffu, s,  o);
        sq += __shfl_xor_sync(0xffffffffu, sq, o);
    }
    float mu  = s * (1.f/128.f);
    float var = sq * (1.f/128.f) - mu*mu;
    float inv = rsqrtf(var + 1e-5f);
    float4 gg = ((const float4*)gam)[lane];
    float4 bb = ((const float4*)bet)[lane];
    float4 o4;
    o4.x = (v.x - mu)*inv*gg.x + bb.x;
    o4.y = (v.y - mu)*inv*gg.y + bb.y;
    o4.z = (v.z - mu)*inv*gg.z + bb.z;
    o4.w = (v.w - mu)*inv*gg.w + bb.w;
    ((float4*)(out + (size_t)row * 128))[lane] = o4;
}

// ---------------- edge preprocessing ----------------
__global__ void hist_k(const void* __restrict__ ei, const void* __restrict__ et) {
    int i = blockIdx.x*blockDim.x + threadIdx.x;
    int stride = gridDim.x*blockDim.x;
    for (; i < Ee; i += stride) {
        int dst = load_int(ei, (long long)Ee + i);
        int rel = load_int(et, i);
        atomicAdd(&g_cnt[dst * Rr + rel], 1);
    }
}

__global__ void scan_k() {   // single block, 1024 threads; exclusive scan of g_cnt -> g_off
    __shared__ int wsum[32];
    __shared__ int s_carry;
    int tid = threadIdx.x, lane = tid & 31, wid = tid >> 5;
    if (tid == 0) s_carry = 0;
    __syncthreads();
    for (int base = 0; base < NRr; base += 1024) {
        int v = g_cnt[base + tid];
        int x = v;
#pragma unroll
        for (int o = 1; o < 32; o <<= 1) {
            int t = __shfl_up_sync(0xffffffffu, x, o);
            if (lane >= o) x += t;
        }
        if (lane == 31) wsum[wid] = x;
        __syncthreads();
        if (wid == 0) {
            int w = wsum[lane];
#pragma unroll
            for (int o = 1; o < 32; o <<= 1) {
                int t = __shfl_up_sync(0xffffffffu, w, o);
                if (lane >= o) w += t;
            }
            wsum[lane] = w;
        }
        __syncthreads();
        int incl = x + (wid ? wsum[wid-1] : 0);
        g_off[base + tid] = s_carry + incl - v;
        __syncthreads();
        if (tid == 1023) s_carry += incl;
        __syncthreads();
    }
    if (tid == 0) g_off[NRr] = s_carry;
}

__global__ void scatter_k(const void* __restrict__ ei, const void* __restrict__ et) {
    int i = blockIdx.x*blockDim.x + threadIdx.x;
    int stride = gridDim.x*blockDim.x;
    for (; i < Ee; i += stride) {
        int dst = load_int(ei, (long long)Ee + i);
        int rel = load_int(et, i);
        int src = load_int(ei, i);
        int seg = dst * Rr + rel;
        int pos = g_off[seg] + atomicAdd(&g_cursor[seg], 1);
        g_srcs[pos] = src;
    }
}

// ---------------- per-segment mean aggregation: warp/segment, no atomics -----
__global__ void agg_k(const float* __restrict__ x) {
    int warp = blockIdx.x * (blockDim.x >> 5) + (threadIdx.x >> 5);
    if (warp >= NRr) return;
    int lane = threadIdx.x & 31;
    int beg = g_off[warp], end = g_off[warp + 1];
    float a0 = 0.f, a1 = 0.f, a2 = 0.f, a3 = 0.f;
    for (int i = beg; i < end; i++) {
        const float* xr = x + (size_t)g_srcs[i] * 128;
        a0 += xr[lane];       a1 += xr[lane + 32];
        a2 += xr[lane + 64];  a3 += xr[lane + 96];
    }
    int c = end - beg;
    float inv = 1.f / (float)(c > 0 ? c : 1);
    int n = warp / Rr, r = warp % Rr;
    float* o = g_agg + (size_t)n * (Rr*Dd) + r * Dd;
    o[lane]      = a0 * inv;  o[lane + 32] = a1 * inv;
    o[lane + 64] = a2 * inv;  o[lane + 96] = a3 * inv;
}

// ---------------- classifier + masked CE; warp per row ----------------
__global__ void cls_k(const float* __restrict__ lm, const float* __restrict__ gx,
                      const float* __restrict__ W, const float* __restrict__ cb,
                      const void* __restrict__ labels, const void* __restrict__ amask,
                      float* __restrict__ logits_out)
{
    __shared__ float s_nll[8];
    __shared__ float s_val[8];
    int wid = threadIdx.x >> 5, lane = threadIdx.x & 31;
    int row = blockIdx.x * 8 + wid;

    // lane holds feat[lane*8 .. lane*8+7] of the 256-wide concat [lm | g]
    float4 f0, f1;
    if (lane < 16) {
        const float* p = lm + (size_t)row * 128 + lane * 8;
        f0 = *(const float4*)p; f1 = *(const float4*)(p + 4);
    } else {
        const float* p = gx + (size_t)row * 128 + (lane - 16) * 8;
        f0 = *(const float4*)p; f1 = *(const float4*)(p + 4);
    }
    float acc[8];
    const float4* W4 = (const float4*)W;   // [8][64 float4]
#pragma unroll
    for (int c = 0; c < 8; c++) {
        float4 w0 = W4[c*64 + lane*2];
        float4 w1 = W4[c*64 + lane*2 + 1];
        acc[c] = f0.x*w0.x + f0.y*w0.y + f0.z*w0.z + f0.w*w0.w
               + f1.x*w1.x + f1.y*w1.y + f1.z*w1.z + f1.w*w1.w;
    }
#pragma unroll
    for (int c = 0; c < 8; c++)
#pragma unroll
        for (int o = 16; o; o >>= 1)
            acc[c] += __shfl_xor_sync(0xffffffffu, acc[c], o);

    if (lane == 0) {
        float lg[8];
#pragma unroll
        for (int c = 0; c < 8; c++) lg[c] = acc[c] + cb[c];
        float mx = lg[0];
#pragma unroll
        for (int c = 1; c < 8; c++) mx = fmaxf(mx, lg[c]);
        float se = 0.f;
#pragma unroll
        for (int c = 0; c < 8; c++) se += expf(lg[c] - mx);
        float lse = mx + logf(se);
#pragma unroll
        for (int c = 0; c < 8; c++) logits_out[(size_t)row * 8 + c] = lg[c];
        int lab = load_int(labels, row);
        bool valid = (load_int(amask, row) == 1);
        s_nll[wid] = valid ? (lse - lg[lab]) : 0.f;
        s_val[wid] = valid ? 1.f : 0.f;
    }
    __syncthreads();
    if (threadIdx.x == 0) {
        float sn = 0.f, sv = 0.f;
#pragma unroll
        for (int i = 0; i < 8; i++) { sn += s_nll[i]; sv += s_val[i]; }
        atomicAdd(&g_loss[0], sn);
        atomicAdd(&g_loss[1], sv);
    }
}

__global__ void fin_k(float* __restrict__ out) {
    out[0] = g_loss[0] / fmaxf(g_loss[1], 1.f);
}

// ---------------- launch ----------------
extern "C" void kernel_launch(void* const* d_in, const int* in_sizes, int n_in,
                              void* d_out, int out_size)
{
    const float* outp   = (const float*)d_in[0];
    const void*  ei     = d_in[1];
    const void*  et     = d_in[2];
    const void*  amask  = d_in[3];
    const void*  labels = d_in[4];
    const float* lm_W   = (const float*)d_in[5];
    const float* lm_b   = (const float*)d_in[6];
    const float* ln_g   = (const float*)d_in[7];
    const float* ln_b   = (const float*)d_in[8];
    const float* W_rel  = (const float*)d_in[9];
    const float* W_root = (const float*)d_in[10];
    const float* conv_b = (const float*)d_in[11];
    const float* cls_W  = (const float*)d_in[12];
    const float* cls_b  = (const float*)d_in[13];
    float* out = (float*)d_out;

    void *p_lm, *p_x, *p_x2, *p_agg, *p_Wt, *p_lg;
    cudaGetSymbolAddress(&p_lm,  g_lm);
    cudaGetSymbolAddress(&p_x,   g_x);
    cudaGetSymbolAddress(&p_x2,  g_x2);
    cudaGetSymbolAddress(&p_agg, g_agg);
    cudaGetSymbolAddress(&p_Wt,  g_Wt);
    cudaGetSymbolAddress(&p_lg,  g_logits_scratch);
    float* lm  = (float*)p_lm;
    float* x1  = (float*)p_x;
    float* x2  = (float*)p_x2;
    float* agg = (float*)p_agg;
    float* Wt  = (float*)p_Wt;

    // dtype probe first: everything integer-typed depends on g_is64
    probe_k<<<1, 256>>>((const int*)ei);
    zero_k<<<96, 1024>>>();
    transW_k<<<512, 256>>>(lm_W);

    // LM head GEMM (relu + bias) -> x2 as pre-LN temp
    gemm_k<<<Nn/128, 256>>>(outp, LMD, Wt, nullptr, 0, nullptr, lm_b, x2);
    ln_k<<<Nn/8, 256>>>(x2, ln_g, ln_b, lm);

    // edge sort (counting sort by segment id)
    hist_k<<<512, 256>>>(ei, et);
    scan_k<<<1, 1024>>>();
    scatter_k<<<512, 256>>>(ei, et);

    // layer 0: aggregate from lm, GEMM(K=384 from agg + K=128 from lm)
    agg_k<<<NRr/8, 256>>>(lm);
    gemm_k<<<Nn/128, 256>>>(agg, Rr*Dd, W_rel,
                            lm, Dd, W_root,
                            conv_b, x1);
    // layer 1
    agg_k<<<NRr/8, 256>>>(x1);
    gemm_k<<<Nn/128, 256>>>(agg, Rr*Dd, W_rel + (size_t)Rr*Dd*Dd,
                            x1, Dd, W_root + (size_t)Dd*Dd,
                            conv_b + Dd, x2);

    // classifier + loss; respect whatever layout out_size implies
    const int LOGITS = Nn * Cc;
    if (out_size >= LOGITS + 1) {
        // loss scalar first, then logits
        cls_k<<<Nn/8, 256>>>(lm, x2, cls_W, cls_b, labels, amask, out + 1);
        fin_k<<<1, 1>>>(out);
    } else if (out_size >= LOGITS) {
        // logits only
        cls_k<<<Nn/8, 256>>>(lm, x2, cls_W, cls_b, labels, amask, out);
    } else {
        // loss only: logits go to device scratch
        cls_k<<<Nn/8, 256>>>(lm, x2, cls_W, cls_b, labels, amask, (float*)p_lg);
        fin_k<<<1, 1>>>(out);
    }
}